// round 10
// baseline (speedup 1.0000x reference)
#include <cuda_runtime.h>

#define NE 1000000
#define NN 500000
#define NT 600000

// Scratch (device globals — no cudaMalloc allowed). 16B-aligned for float4/red.v4.
__device__ __align__(16) float g_y[(size_t)NN * 64];   // node accum, then ytilde = y@w0 in-place
__device__ __align__(16) float g_z1[(size_t)NE * 64];  // z1 accumulator
__device__ int g_en[(size_t)NE * 2];                   // normalized int32 edge_nodes
__device__ int g_te[(size_t)NT * 3];                   // normalized int32 tri_edges

// Vectorized fp32 reduction (no return) — 1 L2 atomic op per 16B (sm_90+)
__device__ __forceinline__ void red_add_v4(float* a, float x, float y, float z, float w) {
    asm volatile("red.global.add.v4.f32 [%0], {%1,%2,%3,%4};"
                 :: "l"(a), "f"(x), "f"(y), "f"(z), "f"(w) : "memory");
}

// K0: normalize indices to int32, auto-detecting whether the source is int64 or
// int32. If int64 (little-endian, values < 2^31), every odd 32-bit word of the
// first 128 words is 0; with random int32 indices that is (1e-6)^64 improbable.
__global__ void __launch_bounds__(256) k_conv(const int* __restrict__ raw,
                                              int* __restrict__ dst, int n) {
    __shared__ int is64;
    if (threadIdx.x == 0) {
        int z = 1;
        for (int k = 1; k < 128; k += 2) z &= (raw[k] == 0);
        is64 = z;
    }
    __syncthreads();
    int i = blockIdx.x * 256 + threadIdx.x;
    if (i < n) dst[i] = is64 ? raw[2 * i] : raw[i];
}

// 4x4-per-thread fp32 GEMM inner loop. As: [64 rows][68 stride], Ws: [64][64].
__device__ __forceinline__ void gemm_4x4(const float* __restrict__ As,
                                         const float* __restrict__ Ws,
                                         int ty, int tx, float acc[4][4]) {
#pragma unroll 4
    for (int k = 0; k < 64; k++) {
        const float4 bv = *(const float4*)&Ws[k * 64 + (tx << 2)];
        float a[4];
#pragma unroll
        for (int i = 0; i < 4; i++) a[i] = As[(ty * 4 + i) * 68 + k];
#pragma unroll
        for (int i = 0; i < 4; i++) {
            acc[i][0] += a[i] * bv.x;
            acc[i][1] += a[i] * bv.y;
            acc[i][2] += a[i] * bv.z;
            acc[i][3] += a[i] * bv.w;
        }
    }
}

// K1: scatter +-x rows into node accumulator y. 16 threads (float4 lanes) per edge.
__global__ void __launch_bounds__(256) k_node_scatter(const float4* __restrict__ x4) {
    long long tid = (long long)blockIdx.x * 256 + threadIdx.x;
    if (tid >= (long long)NE * 16) return;
    int e = (int)(tid >> 4), q = (int)(tid & 15);
    float4 v = x4[(size_t)e * 16 + q];
    int t = g_en[2 * (size_t)e];
    int h = g_en[2 * (size_t)e + 1];
    red_add_v4(g_y + (size_t)t * 64 + q * 4, -v.x, -v.y, -v.z, -v.w);
    red_add_v4(g_y + (size_t)h * 64 + q * 4,  v.x,  v.y,  v.z,  v.w);
}

// K2: ytilde = y @ w0, in place (64 block-private rows per block).
__global__ void __launch_bounds__(256) k_node_gemm(const float* __restrict__ w0) {
    __shared__ float Ws[64 * 64];
    __shared__ float As[64 * 68];
    int tid = threadIdx.x;
    size_t row0 = (size_t)blockIdx.x * 64;
    for (int i = tid; i < 1024; i += 256) ((float4*)Ws)[i] = ((const float4*)w0)[i];
    for (int i = tid; i < 1024; i += 256) {
        int r = i >> 4, q = i & 15;
        float4 v = make_float4(0.f, 0.f, 0.f, 0.f);
        if (row0 + r < NN) v = *(const float4*)&g_y[(row0 + r) * 64 + q * 4];
        *(float4*)&As[r * 68 + q * 4] = v;
    }
    __syncthreads();
    int ty = tid >> 4, tx = tid & 15;
    float acc[4][4] = {};
    gemm_4x4(As, Ws, ty, tx, acc);
#pragma unroll
    for (int i = 0; i < 4; i++) {
        size_t r = row0 + ty * 4 + i;
        if (r < NN)
            *(float4*)&g_y[r * 64 + tx * 4] =
                make_float4(acc[i][0], acc[i][1], acc[i][2], acc[i][3]);
    }
}

// K3: per triangle: w = x[e0]-x[e1]+x[e2]; p = w@w2; scatter +p,-p,+p into z1.
__global__ void __launch_bounds__(256) k_tri(const float4* __restrict__ x4,
                                             const float* __restrict__ w2) {
    __shared__ float Ws[64 * 64];
    __shared__ float As[64 * 68];
    __shared__ int   se[192];
    int tid = threadIdx.x;
    size_t t0 = (size_t)blockIdx.x * 64;
    for (int i = tid; i < 1024; i += 256) ((float4*)Ws)[i] = ((const float4*)w2)[i];
    if (tid < 192) se[tid] = g_te[t0 * 3 + tid];
    __syncthreads();
    for (int i = tid; i < 1024; i += 256) {
        int r = i >> 4, q = i & 15;
        int e0 = se[r * 3], e1 = se[r * 3 + 1], e2 = se[r * 3 + 2];
        float4 a = x4[(size_t)e0 * 16 + q];
        float4 b = x4[(size_t)e1 * 16 + q];
        float4 c = x4[(size_t)e2 * 16 + q];
        *(float4*)&As[r * 68 + q * 4] =
            make_float4(a.x - b.x + c.x, a.y - b.y + c.y, a.z - b.z + c.z, a.w - b.w + c.w);
    }
    __syncthreads();
    int ty = tid >> 4, tx = tid & 15;
    float acc[4][4] = {};
    gemm_4x4(As, Ws, ty, tx, acc);
    __syncthreads();  // all As reads done before overwrite
#pragma unroll
    for (int i = 0; i < 4; i++)
        *(float4*)&As[(ty * 4 + i) * 68 + tx * 4] =
            make_float4(acc[i][0], acc[i][1], acc[i][2], acc[i][3]);
    __syncthreads();
    for (int i = tid; i < 1024; i += 256) {
        int r = i >> 4, q = i & 15;
        float4 p = *(const float4*)&As[r * 68 + q * 4];
        int e0 = se[r * 3], e1 = se[r * 3 + 1], e2 = se[r * 3 + 2];
        red_add_v4(g_z1 + (size_t)e0 * 64 + q * 4,  p.x,  p.y,  p.z,  p.w);
        red_add_v4(g_z1 + (size_t)e1 * 64 + q * 4, -p.x, -p.y, -p.z, -p.w);
        red_add_v4(g_z1 + (size_t)e2 * 64 + q * 4,  p.x,  p.y,  p.z,  p.w);
    }
}

// K4: out = tanh(x@w1 + z1 + ytilde[head] - ytilde[tail]).
__global__ void __launch_bounds__(256) k_final(const float4* __restrict__ x4,
                                               const float* __restrict__ w1,
                                               float* __restrict__ out) {
    __shared__ float Ws[64 * 64];
    __shared__ float As[64 * 68];
    int tid = threadIdx.x;
    size_t r0 = (size_t)blockIdx.x * 64;
    for (int i = tid; i < 1024; i += 256) ((float4*)Ws)[i] = ((const float4*)w1)[i];
    for (int i = tid; i < 1024; i += 256) {
        int r = i >> 4, q = i & 15;
        *(float4*)&As[r * 68 + q * 4] = x4[(r0 + r) * 16 + q];
    }
    __syncthreads();
    int ty = tid >> 4, tx = tid & 15;
    float acc[4][4] = {};
    gemm_4x4(As, Ws, ty, tx, acc);
#pragma unroll
    for (int i = 0; i < 4; i++) {
        size_t r = r0 + ty * 4 + i;
        int t = g_en[2 * r];
        int h = g_en[2 * r + 1];
        const float4 z1v = *(const float4*)&g_z1[r * 64 + tx * 4];
        const float4 yh  = *(const float4*)&g_y[(size_t)h * 64 + tx * 4];
        const float4 yt  = *(const float4*)&g_y[(size_t)t * 64 + tx * 4];
        float4 o;
        o.x = tanhf(acc[i][0] + z1v.x + yh.x - yt.x);
        o.y = tanhf(acc[i][1] + z1v.y + yh.y - yt.y);
        o.z = tanhf(acc[i][2] + z1v.z + yh.z - yt.z);
        o.w = tanhf(acc[i][3] + z1v.w + yh.w - yt.w);
        *(float4*)&out[r * 64 + tx * 4] = o;
    }
}

extern "C" void kernel_launch(void* const* d_in, const int* in_sizes, int n_in,
                              void* d_out, int out_size) {
    // Resolve inputs by element count (robust to ordering):
    //   x: 64,000,000  edge_nodes: 2,000,000  tri_edges: 1,800,000  w: 4,096 (x3, in order)
    const float* x = nullptr;
    const int* en_raw = nullptr;
    const int* te_raw = nullptr;
    const float* w[3] = {nullptr, nullptr, nullptr};
    int wi = 0;
    for (int i = 0; i < n_in; i++) {
        switch (in_sizes[i]) {
            case 64000000: x = (const float*)d_in[i]; break;
            case 2000000:  en_raw = (const int*)d_in[i]; break;
            case 1800000:  te_raw = (const int*)d_in[i]; break;
            case 4096:     if (wi < 3) w[wi++] = (const float*)d_in[i]; break;
            default: break;
        }
    }
    const float* w0 = w[0];
    const float* w1 = w[1];
    const float* w2 = w[2];
    float* out = (float*)d_out;

    void *py = nullptr, *pz = nullptr, *pen = nullptr, *pte = nullptr;
    cudaGetSymbolAddress(&py, g_y);
    cudaGetSymbolAddress(&pz, g_z1);
    cudaGetSymbolAddress(&pen, g_en);
    cudaGetSymbolAddress(&pte, g_te);
    cudaMemsetAsync(py, 0, (size_t)NN * 64 * sizeof(float));
    cudaMemsetAsync(pz, 0, (size_t)NE * 64 * sizeof(float));

    k_conv<<<(NE * 2 + 255) / 256, 256>>>(en_raw, (int*)pen, NE * 2);
    k_conv<<<(NT * 3 + 255) / 256, 256>>>(te_raw, (int*)pte, NT * 3);

    k_node_scatter<<<(NE * 16 + 255) / 256, 256>>>((const float4*)x);
    k_node_gemm<<<(NN + 63) / 64, 256>>>(w0);
    k_tri<<<NT / 64, 256>>>((const float4*)x, w2);
    k_final<<<NE / 64, 256>>>((const float4*)x, w1, out);
}

// round 11
// speedup vs baseline: 1.0139x; 1.0139x over previous
#include <cuda_runtime.h>

#define NE 1000000
#define NN 500000
#define NT 600000

// Scratch (device globals — no cudaMalloc allowed). 16B-aligned for float4/red.v4.
__device__ __align__(16) float g_y[(size_t)NN * 64];   // node accum, then ytilde = y@w0 in-place
__device__ __align__(16) float g_z1[(size_t)NE * 64];  // z1 accumulator
__device__ int g_en[(size_t)NE * 2];                   // normalized int32 edge_nodes
__device__ int g_te[(size_t)NT * 3];                   // normalized int32 tri_edges

// Vectorized fp32 reduction (no return) — 1 L2 atomic op per 16B (sm_90+)
__device__ __forceinline__ void red_add_v4(float* a, float x, float y, float z, float w) {
    asm volatile("red.global.add.v4.f32 [%0], {%1,%2,%3,%4};"
                 :: "l"(a), "f"(x), "f"(y), "f"(z), "f"(w) : "memory");
}

// K0: normalize indices to int32, auto-detecting int64 vs int32 source.
__global__ void __launch_bounds__(256) k_conv(const int* __restrict__ raw,
                                              int* __restrict__ dst, int n) {
    __shared__ int is64;
    if (threadIdx.x == 0) {
        int z = 1;
        for (int k = 1; k < 128; k += 2) z &= (raw[k] == 0);
        is64 = z;
    }
    __syncthreads();
    int i = blockIdx.x * 256 + threadIdx.x;
    if (i < n) dst[i] = is64 ? raw[2 * i] : raw[i];
}

// 4x4-per-thread fp32 GEMM inner loop. As: [64 rows][68 stride], Ws: [64][64].
__device__ __forceinline__ void gemm_4x4(const float* __restrict__ As,
                                         const float* __restrict__ Ws,
                                         int ty, int tx, float acc[4][4]) {
#pragma unroll 4
    for (int k = 0; k < 64; k++) {
        const float4 bv = *(const float4*)&Ws[k * 64 + (tx << 2)];
        float a[4];
#pragma unroll
        for (int i = 0; i < 4; i++) a[i] = As[(ty * 4 + i) * 68 + k];
#pragma unroll
        for (int i = 0; i < 4; i++) {
            acc[i][0] += a[i] * bv.x;
            acc[i][1] += a[i] * bv.y;
            acc[i][2] += a[i] * bv.z;
            acc[i][3] += a[i] * bv.w;
        }
    }
}

// K1: scatter +-x rows into node accumulator y. 16 threads (float4 lanes) per edge.
__global__ void __launch_bounds__(256) k_node_scatter(const float4* __restrict__ x4) {
    long long tid = (long long)blockIdx.x * 256 + threadIdx.x;
    if (tid >= (long long)NE * 16) return;
    int e = (int)(tid >> 4), q = (int)(tid & 15);
    float4 v = x4[(size_t)e * 16 + q];
    int t = g_en[2 * (size_t)e];
    int h = g_en[2 * (size_t)e + 1];
    red_add_v4(g_y + (size_t)t * 64 + q * 4, -v.x, -v.y, -v.z, -v.w);
    red_add_v4(g_y + (size_t)h * 64 + q * 4,  v.x,  v.y,  v.z,  v.w);
}

// K2: ytilde = y @ w0, in place (64 block-private rows per block).
__global__ void __launch_bounds__(256) k_node_gemm(const float* __restrict__ w0) {
    __shared__ float Ws[64 * 64];
    __shared__ float As[64 * 68];
    int tid = threadIdx.x;
    size_t row0 = (size_t)blockIdx.x * 64;
    for (int i = tid; i < 1024; i += 256) ((float4*)Ws)[i] = ((const float4*)w0)[i];
    for (int i = tid; i < 1024; i += 256) {
        int r = i >> 4, q = i & 15;
        float4 v = make_float4(0.f, 0.f, 0.f, 0.f);
        if (row0 + r < NN) v = *(const float4*)&g_y[(row0 + r) * 64 + q * 4];
        *(float4*)&As[r * 68 + q * 4] = v;
    }
    __syncthreads();
    int ty = tid >> 4, tx = tid & 15;
    float acc[4][4] = {};
    gemm_4x4(As, Ws, ty, tx, acc);
#pragma unroll
    for (int i = 0; i < 4; i++) {
        size_t r = row0 + ty * 4 + i;
        if (r < NN)
            *(float4*)&g_y[r * 64 + tx * 4] =
                make_float4(acc[i][0], acc[i][1], acc[i][2], acc[i][3]);
    }
}

// K3: per triangle: w = x[e0]-x[e1]+x[e2]; p = w@w2; scatter +p,-p,+p into z1.
__global__ void __launch_bounds__(256) k_tri(const float4* __restrict__ x4,
                                             const float* __restrict__ w2) {
    __shared__ float Ws[64 * 64];
    __shared__ float As[64 * 68];
    __shared__ int   se[192];
    int tid = threadIdx.x;
    size_t t0 = (size_t)blockIdx.x * 64;
    for (int i = tid; i < 1024; i += 256) ((float4*)Ws)[i] = ((const float4*)w2)[i];
    if (tid < 192) se[tid] = g_te[t0 * 3 + tid];
    __syncthreads();
    for (int i = tid; i < 1024; i += 256) {
        int r = i >> 4, q = i & 15;
        int e0 = se[r * 3], e1 = se[r * 3 + 1], e2 = se[r * 3 + 2];
        float4 a = x4[(size_t)e0 * 16 + q];
        float4 b = x4[(size_t)e1 * 16 + q];
        float4 c = x4[(size_t)e2 * 16 + q];
        *(float4*)&As[r * 68 + q * 4] =
            make_float4(a.x - b.x + c.x, a.y - b.y + c.y, a.z - b.z + c.z, a.w - b.w + c.w);
    }
    __syncthreads();
    int ty = tid >> 4, tx = tid & 15;
    float acc[4][4] = {};
    gemm_4x4(As, Ws, ty, tx, acc);
    __syncthreads();  // all As reads done before overwrite
#pragma unroll
    for (int i = 0; i < 4; i++)
        *(float4*)&As[(ty * 4 + i) * 68 + tx * 4] =
            make_float4(acc[i][0], acc[i][1], acc[i][2], acc[i][3]);
    __syncthreads();
    for (int i = tid; i < 1024; i += 256) {
        int r = i >> 4, q = i & 15;
        float4 p = *(const float4*)&As[r * 68 + q * 4];
        int e0 = se[r * 3], e1 = se[r * 3 + 1], e2 = se[r * 3 + 2];
        red_add_v4(g_z1 + (size_t)e0 * 64 + q * 4,  p.x,  p.y,  p.z,  p.w);
        red_add_v4(g_z1 + (size_t)e1 * 64 + q * 4, -p.x, -p.y, -p.z, -p.w);
        red_add_v4(g_z1 + (size_t)e2 * 64 + q * 4,  p.x,  p.y,  p.z,  p.w);
    }
}

// K4: out = tanh(x@w1 + z1 + ytilde[head] - ytilde[tail]).
__global__ void __launch_bounds__(256) k_final(const float4* __restrict__ x4,
                                               const float* __restrict__ w1,
                                               float* __restrict__ out) {
    __shared__ float Ws[64 * 64];
    __shared__ float As[64 * 68];
    int tid = threadIdx.x;
    size_t r0 = (size_t)blockIdx.x * 64;
    for (int i = tid; i < 1024; i += 256) ((float4*)Ws)[i] = ((const float4*)w1)[i];
    for (int i = tid; i < 1024; i += 256) {
        int r = i >> 4, q = i & 15;
        *(float4*)&As[r * 68 + q * 4] = x4[(r0 + r) * 16 + q];
    }
    __syncthreads();
    int ty = tid >> 4, tx = tid & 15;
    float acc[4][4] = {};
    gemm_4x4(As, Ws, ty, tx, acc);
#pragma unroll
    for (int i = 0; i < 4; i++) {
        size_t r = r0 + ty * 4 + i;
        int t = g_en[2 * r];
        int h = g_en[2 * r + 1];
        const float4 z1v = *(const float4*)&g_z1[r * 64 + tx * 4];
        const float4 yh  = *(const float4*)&g_y[(size_t)h * 64 + tx * 4];
        const float4 yt  = *(const float4*)&g_y[(size_t)t * 64 + tx * 4];
        float4 o;
        o.x = tanhf(acc[i][0] + z1v.x + yh.x - yt.x);
        o.y = tanhf(acc[i][1] + z1v.y + yh.y - yt.y);
        o.z = tanhf(acc[i][2] + z1v.z + yh.z - yt.z);
        o.w = tanhf(acc[i][3] + z1v.w + yh.w - yt.w);
        *(float4*)&out[r * 64 + tx * 4] = o;
    }
}

extern "C" void kernel_launch(void* const* d_in, const int* in_sizes, int n_in,
                              void* d_out, int out_size) {
    // Resolve inputs by element count (robust to ordering):
    //   x: 64,000,000  edge_nodes: 2,000,000  tri_edges: 1,800,000  w: 4,096 (x3, in order)
    const float* x = nullptr;
    const int* en_raw = nullptr;
    const int* te_raw = nullptr;
    const float* w[3] = {nullptr, nullptr, nullptr};
    int wi = 0;
    for (int i = 0; i < n_in; i++) {
        switch (in_sizes[i]) {
            case 64000000: x = (const float*)d_in[i]; break;
            case 2000000:  en_raw = (const int*)d_in[i]; break;
            case 1800000:  te_raw = (const int*)d_in[i]; break;
            case 4096:     if (wi < 3) w[wi++] = (const float*)d_in[i]; break;
            default: break;
        }
    }
    const float* w0 = w[0];
    const float* w1 = w[1];
    const float* w2 = w[2];
    float* out = (float*)d_out;

    void *py = nullptr, *pz = nullptr, *pen = nullptr, *pte = nullptr;
    cudaGetSymbolAddress(&py, g_y);
    cudaGetSymbolAddress(&pz, g_z1);
    cudaGetSymbolAddress(&pen, g_en);
    cudaGetSymbolAddress(&pte, g_te);

    // Fork/join streams (created once, on the first — non-captured — call;
    // during graph capture only event/kernel/memset nodes are recorded).
    static cudaStream_t sA = nullptr, sB = nullptr;
    static cudaEvent_t evRoot = nullptr, evA = nullptr, evB = nullptr;
    if (sA == nullptr) {
        cudaStreamCreateWithFlags(&sA, cudaStreamNonBlocking);
        cudaStreamCreateWithFlags(&sB, cudaStreamNonBlocking);
        cudaEventCreateWithFlags(&evRoot, cudaEventDisableTiming);
        cudaEventCreateWithFlags(&evA, cudaEventDisableTiming);
        cudaEventCreateWithFlags(&evB, cudaEventDisableTiming);
    }

    // Fork from the capture-origin (default) stream.
    cudaEventRecord(evRoot, 0);
    cudaStreamWaitEvent(sA, evRoot, 0);
    cudaStreamWaitEvent(sB, evRoot, 0);

    // Branch A — node pipeline: memset y -> conv en -> scatter -> y@w0.
    cudaMemsetAsync(py, 0, (size_t)NN * 64 * sizeof(float), sA);
    k_conv<<<(NE * 2 + 255) / 256, 256, 0, sA>>>(en_raw, (int*)pen, NE * 2);
    k_node_scatter<<<(NE * 16 + 255) / 256, 256, 0, sA>>>((const float4*)x);
    k_node_gemm<<<(NN + 63) / 64, 256, 0, sA>>>(w0);
    cudaEventRecord(evA, sA);

    // Branch B — triangle pipeline: memset z1 -> conv te -> tri GEMM + scatter.
    cudaMemsetAsync(pz, 0, (size_t)NE * 64 * sizeof(float), sB);
    k_conv<<<(NT * 3 + 255) / 256, 256, 0, sB>>>(te_raw, (int*)pte, NT * 3);
    k_tri<<<NT / 64, 256, 0, sB>>>((const float4*)x, w2);
    cudaEventRecord(evB, sB);

    // Join on the default stream, then the fused final GEMM + epilogue.
    cudaStreamWaitEvent(0, evA, 0);
    cudaStreamWaitEvent(0, evB, 0);
    k_final<<<NE / 64, 256>>>((const float4*)x, w1, out);
}